// round 13
// baseline (speedup 1.0000x reference)
#include <cuda_runtime.h>
#include <math.h>

#define DIMN 16
#define NSEC 16
#define NSUB 16
#define NE   256
#define NB   128
#define NSL  64

// ---- output layout (flattened tuple, fp32) ----
#define OUT_TZ1    0
#define OUT_TZ2    1024
#define OUT_FWD    2048
#define OUT_EQ     18432
#define OUT_ATTN   18433
#define OUT_ORTH   35841
#define OUT_PAR    35842
#define OUT_COMMUT 35843
#define OUT_SPARSE 35844
#define OUT_SECTOR 35845
#define OUT_SUB    35846

// accumulators
#define ACC_PAR    0
#define ACC_ORTH   1
#define ACC_SPARSE 2
#define ACC_SECTOR 3
#define ACC_EQ     4

// ---- packed f32x2 ops (sm_103a) ----
#define PACK2(o, x, y)   asm("mov.b64 %0, {%1, %2};" : "=l"(o) : "f"(x), "f"(y))
#define UNPACK2(x, y, v) asm("mov.b64 {%0, %1}, %2;" : "=f"(x), "=f"(y) : "l"(v))
#define FMA2(d, a, b)    asm("fma.rn.f32x2 %0, %1, %2, %0;" : "+l"(d) : "l"(a), "l"(b))
#define FMA2SQ(d, a, c)  asm("fma.rn.f32x2 %0, %1, %1, %2;" : "=l"(d) : "l"(a), "l"(c))
#define MUL2(d, a, b)    asm("mul.rn.f32x2 %0, %1, %2;" : "=l"(d) : "l"(a), "l"(b))

// ---- scratch (__device__ globals; referenced ONLY from device code) ----
__device__ float  g_diff[NE * NB * DIMN];  // [e][b][d]
__device__ float  g_invnrm[NSEC * 2048];   // [s][m], m = u*128 + b
__device__ float  g_w[NSL * NE];           // switch*fprob
__device__ float  g_invsyms[NSL * 256];
__device__ float  g_c[256];                // commut c[a*16+b]
__device__ double g_acc[8];

__global__ void k_zero() {
    if (threadIdx.x < 8) g_acc[threadIdx.x] = 0.0;
}

// ---- fused: expm(ge[e]) (Taylor13 + scaling/squaring) -> diff/invnrm/sparse ----
__global__ void k_expmdiff(const float* __restrict__ ge, const float* __restrict__ z)
{
    __shared__ float sA[256];
    __shared__ float sT[256];
    __shared__ float sS[256];
    __shared__ float rowsum[16];
    __shared__ int s_sq;
    __shared__ double red[128];
    int t = threadIdx.x;
    int i = t >> 4, j = t & 15;
    int e = blockIdx.x;

    float a = ge[e * 256 + t];
    sA[t] = fabsf(a);
    __syncthreads();
    if (j == 0) {
        float rs = 0.f;
        #pragma unroll
        for (int k = 0; k < 16; k++) rs += sA[i * 16 + k];
        rowsum[i] = rs;
    }
    __syncthreads();
    if (t == 0) {
        float mx = 0.f;
        #pragma unroll
        for (int k = 0; k < 16; k++) mx = fmaxf(mx, rowsum[k]);
        int s = 0;
        while (mx > 0.25f && s < 60) { mx *= 0.5f; s++; }
        s_sq = s;
    }
    __syncthreads();
    int sc = s_sq;
    a = ldexpf(a, -sc);
    sA[t] = a;
    sT[t] = a;
    float pv = ((i == j) ? 1.0f : 0.0f) + a;
    __syncthreads();
    for (int k = 2; k <= 13; k++) {
        float nt = 0.f;
        #pragma unroll
        for (int kk = 0; kk < 16; kk++)
            nt += sT[i * 16 + kk] * sA[kk * 16 + j];
        nt *= (1.0f / (float)k);
        __syncthreads();
        sT[t] = nt;
        pv += nt;
        __syncthreads();
    }
    for (int it = 0; it < sc; it++) {
        sS[t] = pv;
        __syncthreads();
        float np = 0.f;
        #pragma unroll
        for (int kk = 0; kk < 16; kk++)
            np += sS[i * 16 + kk] * sS[kk * 16 + j];
        pv = np;
        __syncthreads();
    }
    sS[t] = pv;   // final sym matrix in shared
    __syncthreads();

    // diff part (threads 0..127 = batch index b)
    if (t < 128) {
        int b = t;
        float zr[16], dv[16];
        #pragma unroll
        for (int k = 0; k < 16; k++) zr[k] = z[b * 16 + k];
        float n2 = 0.f, mx = 0.f;
        #pragma unroll
        for (int d = 0; d < 16; d++) {
            float m = 0.f;
            #pragma unroll
            for (int k = 0; k < 16; k++) m += zr[k] * sS[k * 16 + d];
            float df = zr[d] - m;
            dv[d] = df;
            float q = df * df;
            n2 += q;
            mx = fmaxf(mx, q);
        }
        #pragma unroll
        for (int d = 0; d < 16; d++) g_diff[e * 2048 + b * 16 + d] = dv[d];
        int s = e >> 4, u = e & 15;
        g_invnrm[s * 2048 + u * 128 + b] = rsqrtf(n2);
        float sp = n2 - mx;
        red[b] = (double)(sp * sp);
    }
    __syncthreads();
    for (int o = 64; o; o >>= 1) {
        if (t < o) red[t] += red[t + o];
        __syncthreads();
    }
    if (t == 0) atomicAdd(&g_acc[ACC_SPARSE], red[0]);
}

// ---- parallel: per-sector Gram + grouped logs; f32x2 FMA; 2 pairs/block ----
// thread (tx,ty): rows ty*8+i, col pairs (2tx+32q, 2tx+32q+1)
__global__ void __launch_bounds__(256, 2) k_parallel()
{
    __shared__ float Am[128][18];
    __shared__ float Bt[16][132];
    __shared__ float im[128], inr[128];
    __shared__ double wred[8];
    int s = blockIdx.y;
    int tid = threadIdx.x;  // 256
    int tx = tid & 15, ty = tid >> 4;
    const float* base = g_diff + s * 32768;
    double total = 0.0;

    unsigned long long E2;
    PACK2(E2, 1e-9f, 1e-9f);

    #pragma unroll 1
    for (int half = 0; half < 2; half++) {
        int p = blockIdx.x + half * 68;  // 0..135
        int ti = 0, rem = p;
        while (rem >= 16 - ti) { rem -= 16 - ti; ti++; }
        int tj = ti + rem;

        if (half) __syncthreads();
        for (int idx = tid; idx < 2048; idx += 256) {
            int r = idx >> 4, d = idx & 15;
            Am[r][d] = base[(ti * 128 + r) * 16 + d];
            Bt[d][r] = base[(tj * 128 + r) * 16 + d];
        }
        if (tid < 128) {
            im[tid]  = g_invnrm[s * 2048 + ti * 128 + tid];
            inr[tid] = g_invnrm[s * 2048 + tj * 128 + tid];
        }
        __syncthreads();

        unsigned long long acc2[8][4];
        #pragma unroll
        for (int i = 0; i < 8; i++)
            #pragma unroll
            for (int q = 0; q < 4; q++) acc2[i][q] = 0ULL;

        #pragma unroll 4
        for (int d = 0; d < 16; d++) {
            unsigned long long a2[8], b2[4];
            #pragma unroll
            for (int i = 0; i < 8; i++) {
                float av = Am[ty * 8 + i][d];
                PACK2(a2[i], av, av);
            }
            #pragma unroll
            for (int q = 0; q < 4; q++)
                b2[q] = *(const unsigned long long*)&Bt[d][2 * tx + 32 * q];
            #pragma unroll
            for (int i = 0; i < 8; i++)
                #pragma unroll
                for (int q = 0; q < 4; q++)
                    FMA2(acc2[i][q], a2[i], b2[q]);
        }

        unsigned long long inr2[4];
        #pragma unroll
        for (int q = 0; q < 4; q++)
            inr2[q] = *(const unsigned long long*)&inr[2 * tx + 32 * q];

        float sum = 0.f;
        if (ti != tj) {
            // all weights 2: grouped logs (-log(prod of 4)), x2 at end
            #pragma unroll
            for (int i = 0; i < 8; i++) {
                float pi = im[ty * 8 + i];
                unsigned long long pi2;
                PACK2(pi2, pi, pi);
                unsigned long long t2[4];
                #pragma unroll
                for (int q = 0; q < 4; q++) {
                    unsigned long long u;
                    MUL2(u, acc2[i][q], pi2);
                    MUL2(u, u, inr2[q]);
                    FMA2SQ(t2[q], u, E2);
                }
                unsigned long long w1, w2;
                MUL2(w1, t2[0], t2[1]);
                MUL2(w2, t2[2], t2[3]);
                float x0, x1, y0, y1;
                UNPACK2(x0, x1, w1);
                UNPACK2(y0, y1, w2);
                sum -= __logf(x0 * x1) + __logf(y0 * y1);
            }
            total += 2.0 * (double)sum;
        } else {
            // diagonal tile: per-element weights 0/1/2
            #pragma unroll
            for (int i = 0; i < 8; i++) {
                int r = ty * 8 + i;
                float pi = im[r];
                #pragma unroll
                for (int q = 0; q < 4; q++) {
                    float d0, d1;
                    UNPACK2(d0, d1, acc2[i][q]);
                    int c0 = 2 * tx + 32 * q, c1 = c0 + 1;
                    float r0 = d0 * pi * inr[c0];
                    float r1 = d1 * pi * inr[c1];
                    float v0 = -__logf(fmaf(r0, r0, 1e-9f));
                    float v1 = -__logf(fmaf(r1, r1, 1e-9f));
                    float w0 = (c0 > r) ? 2.0f : ((c0 == r) ? 1.0f : 0.0f);
                    float w1w = (c1 > r) ? 2.0f : ((c1 == r) ? 1.0f : 0.0f);
                    sum += w0 * v0 + w1w * v1;
                }
            }
            total += (double)sum;
        }
    }

    // warp shuffle reduce (double), then warp0 reduces 8 partials
    #pragma unroll
    for (int o = 16; o; o >>= 1) total += __shfl_xor_sync(0xffffffffu, total, o);
    if ((tid & 31) == 0) wred[tid >> 5] = total;
    __syncthreads();
    if (tid < 32) {
        double v = (tid < 8) ? wred[tid] : 0.0;
        #pragma unroll
        for (int o = 4; o; o >>= 1) v += __shfl_xor_sync(0xffffffffu, v, o);
        if (tid == 0) atomicAdd(&g_acc[ACC_PAR], v);
    }
}

// ---- orth: cross-sector Gram of selected sub-sector rows; 8x8 tiling ----
__global__ void k_orth(const int* __restrict__ sec_idx)
{
    __shared__ float A[128][17];
    __shared__ float B[128][17];
    __shared__ float ia[128], ib[128];
    __shared__ double wred[8];
    int bx = blockIdx.x;  // 0..119, pairs s1<s2
    int s1 = 0, rem = bx;
    while (rem >= 15 - s1) { rem -= 15 - s1; s1++; }
    int s2 = s1 + 1 + rem;
    int tid = threadIdx.x;
    int tx = tid & 15, ty = tid >> 4;
    int u1 = sec_idx[s1], u2 = sec_idx[s2];
    const float* pa = g_diff + s1 * 32768 + u1 * 2048;
    const float* pb = g_diff + s2 * 32768 + u2 * 2048;
    for (int idx = tid; idx < 2048; idx += 256) {
        int r = idx >> 4, d = idx & 15;
        A[r][d] = pa[r * 16 + d];
        B[r][d] = pb[r * 16 + d];
    }
    if (tid < 128) {
        ia[tid] = g_invnrm[s1 * 2048 + u1 * 128 + tid];
        ib[tid] = g_invnrm[s2 * 2048 + u2 * 128 + tid];
    }
    __syncthreads();

    float acc[8][8];
    #pragma unroll
    for (int i = 0; i < 8; i++)
        #pragma unroll
        for (int j = 0; j < 8; j++) acc[i][j] = 0.f;

    #pragma unroll
    for (int d = 0; d < 16; d++) {
        float af[8], bf[8];
        #pragma unroll
        for (int i = 0; i < 8; i++) af[i] = A[ty * 8 + i][d];
        #pragma unroll
        for (int j = 0; j < 8; j++) bf[j] = B[tx + 16 * j][d];
        #pragma unroll
        for (int i = 0; i < 8; i++)
            #pragma unroll
            for (int j = 0; j < 8; j++)
                acc[i][j] = fmaf(af[i], bf[j], acc[i][j]);
    }

    float ias[8], ibs[8];
    #pragma unroll
    for (int i = 0; i < 8; i++) ias[i] = ia[ty * 8 + i];
    #pragma unroll
    for (int j = 0; j < 8; j++) ibs[j] = ib[tx + 16 * j];

    float sum = 0.f;
    #pragma unroll
    for (int i = 0; i < 8; i++)
        #pragma unroll
        for (int j = 0; j < 8; j++) {
            float ratio = acc[i][j] * ias[i] * ibs[j];
            sum += ratio * ratio;
        }
    double total = (double)sum;
    #pragma unroll
    for (int o = 16; o; o >>= 1) total += __shfl_xor_sync(0xffffffffu, total, o);
    if ((tid & 31) == 0) wred[tid >> 5] = total;
    __syncthreads();
    if (tid < 32) {
        double v = (tid < 8) ? wred[tid] : 0.0;
        #pragma unroll
        for (int o = 4; o; o >>= 1) v += __shfl_xor_sync(0xffffffffu, v, o);
        if (tid == 0) atomicAdd(&g_acc[ACC_ORTH], v);
    }
}

// ---- linear head: prob, sector loss, switch, fprob, w ----
__global__ void k_head(const float* __restrict__ mean, const float* __restrict__ logvar,
                       const float* __restrict__ z, const float* __restrict__ lw,
                       const float* __restrict__ lb, const float* __restrict__ gn,
                       float* __restrict__ out)
{
    __shared__ float feat[64];
    __shared__ float prob[288];
    __shared__ double lred[16];
    int b = blockIdx.x, t = threadIdx.x;  // 288 threads
    if (t < 16)      feat[t] = mean[b * 16 + t];
    else if (t < 32) feat[t] = expf(0.5f * logvar[b * 16 + (t - 16)]);
    else if (t < 48) feat[t] = mean[(64 + b) * 16 + (t - 32)];
    else if (t < 64) feat[t] = expf(0.5f * mean[(64 + b) * 16 + (t - 48)]);
    __syncthreads();
    {
        float acc = lb[t];
        #pragma unroll 8
        for (int k = 0; k < 64; k++) acc += feat[k] * lw[t * 64 + k];
        prob[t] = acc;
    }
    __syncthreads();
    if (t < 16) {
        int s = t;
        float l0 = prob[2 * s], l1 = prob[2 * s + 1];
        float m = fmaxf(l0, l1);
        float e0 = expf(l0 - m), e1 = expf(l1 - m);
        float inv = 1.0f / (e0 + e1);
        float p0 = e0 * inv, p1 = e1 * inv;
        // log_softmax of the softmax output (quirk kept from reference)
        float m2 = fmaxf(p0, p1);
        float lse = m2 + logf(expf(p0 - m2) + expf(p1 - m2));
        float zd = z[b * 16 + s] - z[(64 + b) * 16 + s];
        int tgt = (fabsf(zd) > 0.2f) ? 1 : 0;
        float ls = (tgt ? p1 : p0) - lse;
        lred[s] = (double)(-ls);
        // gumbel attn, tau = 1e-4
        int r = b * 16 + s;
        float g0 = gn[2 * r], g1 = gn[2 * r + 1];
        float x0 = (l0 + g0) * 10000.0f, x1 = (l1 + g1) * 10000.0f;
        float a1 = 1.0f / (1.0f + expf(x0 - x1));
        float a0 = 1.0f / (1.0f + expf(x1 - x0));
        float sw = ((a0 >= 0.5f) || (a1 > 0.5f)) ? a1 : 0.0f;
        out[OUT_ATTN + b * 272 + s] = sw;
        // fprob softmax over 16 sub-entries
        float f[16];
        float fm = -3.0e38f;
        #pragma unroll
        for (int u = 0; u < 16; u++) { f[u] = prob[32 + s * 16 + u]; fm = fmaxf(fm, f[u]); }
        float sum = 0.f;
        #pragma unroll
        for (int u = 0; u < 16; u++) { f[u] = expf(f[u] - fm); sum += f[u]; }
        float invs = 1.0f / sum;
        #pragma unroll
        for (int u = 0; u < 16; u++) {
            float fp = f[u] * invs;
            out[OUT_ATTN + b * 272 + 16 + s * 16 + u] = fp;
            g_w[b * 256 + s * 16 + u] = sw * fp;
        }
    }
    __syncthreads();
    if (t == 0) {
        double sl = 0.0;
        for (int s = 0; s < 16; s++) sl += lred[s];
        atomicAdd(&g_acc[ACC_SECTOR], sl);
    }
}

// ---- sub_syms: one block per sector; ge slice + w slice cached in shared ----
__global__ void k_syms2(const float* __restrict__ ge, float* __restrict__ out)
{
    __shared__ float geS[16][256];
    __shared__ float wsh[64][16];
    int s = blockIdx.x, t = threadIdx.x;  // 256 threads
    #pragma unroll
    for (int u = 0; u < 16; u++)
        geS[u][t] = ge[(s * 16 + u) * 256 + t];
    for (int idx = t; idx < 64 * 16; idx += 256)
        wsh[idx >> 4][idx & 15] = g_w[(idx >> 4) * 256 + s * 16 + (idx & 15)];
    __syncthreads();
    #pragma unroll 4
    for (int b = 0; b < 64; b++) {
        float sub = 0.f;
        #pragma unroll
        for (int u = 0; u < 16; u++)
            sub = fmaf(wsh[b][u], geS[u][t], sub);
        out[OUT_SUB + b * 4096 + s * 256 + t] = sub;
    }
}

// ---- expm of S: 128 blocks; S = sum of sub_syms read from out ----
// blk<64 -> fwd (out+FWD), else inv -> g_invsyms
__global__ void k_expmS(float* __restrict__ out)
{
    __shared__ float sA[256];
    __shared__ float sT[256];
    __shared__ float sP[256];
    __shared__ float rowsum[16];
    __shared__ int s_sq;
    int t = threadIdx.x;
    int i = t >> 4, j = t & 15;
    int blk = blockIdx.x;
    int m = blk & 63;
    int invm = blk >> 6;
    float sign = invm ? -1.0f : 1.0f;
    float* dst = invm ? (g_invsyms + m * 256) : (out + OUT_FWD + m * 256);

    float Sv = 0.f;
    #pragma unroll
    for (int s = 0; s < 16; s++)
        Sv += out[OUT_SUB + m * 4096 + s * 256 + t];
    float a = sign * Sv;
    sA[t] = fabsf(a);
    __syncthreads();
    if (j == 0) {
        float rs = 0.f;
        #pragma unroll
        for (int k = 0; k < 16; k++) rs += sA[i * 16 + k];
        rowsum[i] = rs;
    }
    __syncthreads();
    if (t == 0) {
        float mx = 0.f;
        #pragma unroll
        for (int k = 0; k < 16; k++) mx = fmaxf(mx, rowsum[k]);
        int s = 0;
        while (mx > 0.25f && s < 60) { mx *= 0.5f; s++; }
        s_sq = s;
    }
    __syncthreads();
    int s = s_sq;
    a = ldexpf(a, -s);
    sA[t] = a;
    sT[t] = a;
    float p = ((i == j) ? 1.0f : 0.0f) + a;
    __syncthreads();
    for (int k = 2; k <= 13; k++) {
        float nt = 0.f;
        #pragma unroll
        for (int kk = 0; kk < 16; kk++)
            nt += sT[i * 16 + kk] * sA[kk * 16 + j];
        nt *= (1.0f / (float)k);
        __syncthreads();
        sT[t] = nt;
        p += nt;
        __syncthreads();
    }
    for (int it = 0; it < s; it++) {
        sP[t] = p;
        __syncthreads();
        float np = 0.f;
        #pragma unroll
        for (int kk = 0; kk < 16; kk++)
            np += sP[i * 16 + kk] * sP[kk * 16 + j];
        p = np;
        __syncthreads();
    }
    dst[t] = p;
}

// ---- tz1/tz2 + equivariant ----
__global__ void k_tz(const float* __restrict__ z, float* __restrict__ out)
{
    int b = blockIdx.x, t = threadIdx.x;  // 32 threads
    float v = 0.f, term;
    if (t < 16) {
        int d = t;
        #pragma unroll
        for (int k = 0; k < 16; k++)
            v += z[b * 16 + k] * out[OUT_FWD + b * 256 + k * 16 + d];
        out[OUT_TZ1 + b * 16 + d] = v;
        float dd = v - z[(64 + b) * 16 + d];  // tz1 - z2
        term = dd * dd;
    } else {
        int d = t - 16;
        #pragma unroll
        for (int k = 0; k < 16; k++)
            v += z[(64 + b) * 16 + k] * g_invsyms[b * 256 + k * 16 + d];
        out[OUT_TZ2 + b * 16 + d] = v;
        float dd = v - z[b * 16 + d];  // tz2 - z1
        term = dd * dd;
    }
    #pragma unroll
    for (int o = 16; o; o >>= 1) term += __shfl_xor_sync(0xffffffffu, term, o);
    if (t == 0) atomicAdd(&g_acc[ACC_EQ], (double)term);
}

// ---- commutator c[a,b] ----
__global__ void k_commut(const float* __restrict__ ge)
{
    __shared__ double red[256];
    int a = blockIdx.x >> 4, b = blockIdx.x & 15;
    int t = threadIdx.x;
    int i = t >> 4, l = t & 15;
    float r1 = 0.f, r2 = 0.f;
    #pragma unroll
    for (int k = 0; k < 16; k++) {
        float h_bl = ge[4096 * k + b * 16 + l];
        float h_al = ge[4096 * k + a * 16 + l];
        r1 += ge[a * 256 + i * 16 + k] * h_bl;
        r2 += ge[b * 256 + i * 16 + k] * h_al;
    }
    float d = r1 - r2;
    red[t] = (double)(d * d);
    __syncthreads();
    for (int o = 128; o; o >>= 1) {
        if (t < o) red[t] += red[t + o];
        __syncthreads();
    }
    if (t == 0) g_c[a * 16 + b] = (float)(2.0 * red[0]);
}

// ---- final scalar writes ----
__global__ void k_final(float* __restrict__ out)
{
    if (threadIdx.x == 0) {
        out[OUT_PAR]    = (float)(g_acc[ACC_PAR] / (16.0 * 2048.0 * 2048.0));
        out[OUT_ORTH]   = (float)(2.0 * g_acc[ACC_ORTH] / (2048.0 * 2048.0));
        out[OUT_SPARSE] = (float)(g_acc[ACC_SPARSE] / 32768.0);
        out[OUT_SECTOR] = (float)(g_acc[ACC_SECTOR] / 64.0);
        out[OUT_EQ]     = (float)(g_acc[ACC_EQ] / 1024.0);
        double cm = 0.0;
        int p = 0;
        for (int a = 0; a < 16; a++)
            for (int b = a + 1; b < 16; b++) {
                cm += (double)g_c[a * 16 + b] * (double)(120 - p);
                p++;
            }
        out[OUT_COMMUT] = (float)(cm / (4096.0 * 4096.0));
    }
}

extern "C" void kernel_launch(void* const* d_in, const int* in_sizes, int n_in,
                              void* d_out, int out_size)
{
    // resolve inputs by element count (robust to metadata ordering)
    int ige = -1, ilw = -1, ilb = -1, isx = -1;
    int i2048[4]; int n2 = 0;
    for (int i = 0; i < n_in; i++) {
        int sz = in_sizes[i];
        if (sz == 65536) ige = i;
        else if (sz == 18432) ilw = i;
        else if (sz == 288) ilb = i;
        else if (sz == 16) isx = i;
        else if (sz == 2048 && n2 < 4) i2048[n2++] = i;
    }
    int imean, ilogvar, iz, ign;
    if (ige == 0) {
        // alphabetical: gumbel_noise, latent_z, logvar, mean
        ign = i2048[0]; iz = i2048[1]; ilogvar = i2048[2]; imean = i2048[3];
    } else {
        // dict/signature order: mean, logvar, latent_z, gumbel_noise
        imean = i2048[0]; ilogvar = i2048[1]; iz = i2048[2]; ign = i2048[3];
    }

    const float* mean   = (const float*)d_in[imean];
    const float* logvar = (const float*)d_in[ilogvar];
    const float* z      = (const float*)d_in[iz];
    const float* ge     = (const float*)d_in[ige];
    const float* lw     = (const float*)d_in[ilw];
    const float* lb     = (const float*)d_in[ilb];
    const float* gn     = (const float*)d_in[ign];
    const int*   sidx   = (const int*)d_in[isx];
    float* out = (float*)d_out;

    // persistent side streams + events for graph-branch parallelism
    static cudaStream_t s1 = 0, s2 = 0, s3 = 0;
    static cudaEvent_t e0 = 0, ed = 0, e1 = 0, e2 = 0, e3 = 0;
    if (s1 == 0) {
        cudaStreamCreateWithFlags(&s1, cudaStreamNonBlocking);
        cudaStreamCreateWithFlags(&s2, cudaStreamNonBlocking);
        cudaStreamCreateWithFlags(&s3, cudaStreamNonBlocking);
        cudaEventCreateWithFlags(&e0, cudaEventDisableTiming);
        cudaEventCreateWithFlags(&ed, cudaEventDisableTiming);
        cudaEventCreateWithFlags(&e1, cudaEventDisableTiming);
        cudaEventCreateWithFlags(&e2, cudaEventDisableTiming);
        cudaEventCreateWithFlags(&e3, cudaEventDisableTiming);
    }

    k_zero<<<1, 32>>>();
    cudaEventRecord(e0, 0);
    cudaStreamWaitEvent(s1, e0, 0);
    cudaStreamWaitEvent(s2, e0, 0);
    cudaStreamWaitEvent(s3, e0, 0);

    // branch A: expm(ge)+diff fused -> parallel
    k_expmdiff<<<256, 256, 0, s1>>>(ge, z);
    cudaEventRecord(ed, s1);
    k_parallel<<<dim3(68, 16), 256, 0, s1>>>();
    cudaEventRecord(e1, s1);

    // branch B: head -> syms2 (per-sector, ge cached in smem) -> expm(S) -> tz
    k_head<<<64, 288, 0, s2>>>(mean, logvar, z, lw, lb, gn, out);
    k_syms2<<<16, 256, 0, s2>>>(ge, out);
    k_expmS<<<128, 256, 0, s2>>>(out);
    k_tz<<<64, 32, 0, s2>>>(z, out);
    cudaEventRecord(e2, s2);

    // branch C: commut; then orth (after diff is ready)
    k_commut<<<256, 256, 0, s3>>>(ge);
    cudaStreamWaitEvent(s3, ed, 0);
    k_orth<<<120, 256, 0, s3>>>(sidx);
    cudaEventRecord(e3, s3);

    // join
    cudaStreamWaitEvent(0, e1, 0);
    cudaStreamWaitEvent(0, e2, 0);
    cudaStreamWaitEvent(0, e3, 0);
    k_final<<<1, 32>>>(out);
}

// round 14
// speedup vs baseline: 1.2311x; 1.2311x over previous
#include <cuda_runtime.h>
#include <math.h>

#define DIMN 16
#define NSEC 16
#define NSUB 16
#define NE   256
#define NB   128
#define NSL  64

// ---- output layout (flattened tuple, fp32) ----
#define OUT_TZ1    0
#define OUT_TZ2    1024
#define OUT_FWD    2048
#define OUT_EQ     18432
#define OUT_ATTN   18433
#define OUT_ORTH   35841
#define OUT_PAR    35842
#define OUT_COMMUT 35843
#define OUT_SPARSE 35844
#define OUT_SECTOR 35845
#define OUT_SUB    35846

// accumulators
#define ACC_PAR    0
#define ACC_ORTH   1
#define ACC_SPARSE 2
#define ACC_SECTOR 3
#define ACC_EQ     4

// ---- packed f32x2 ops (sm_103a) ----
#define PACK2(o, x, y)   asm("mov.b64 %0, {%1, %2};" : "=l"(o) : "f"(x), "f"(y))
#define UNPACK2(x, y, v) asm("mov.b64 {%0, %1}, %2;" : "=f"(x), "=f"(y) : "l"(v))
#define FMA2(d, a, b)    asm("fma.rn.f32x2 %0, %1, %2, %0;" : "+l"(d) : "l"(a), "l"(b))
#define FMA2SQ(d, a, c)  asm("fma.rn.f32x2 %0, %1, %1, %2;" : "=l"(d) : "l"(a), "l"(c))
#define MUL2(d, a, b)    asm("mul.rn.f32x2 %0, %1, %2;" : "=l"(d) : "l"(a), "l"(b))

// ---- scratch (__device__ globals; referenced ONLY from device code) ----
__device__ float  g_diff[NE * NB * DIMN];  // [e][b][d]
__device__ float  g_invnrm[NSEC * 2048];   // [s][m], m = u*128 + b
__device__ float  g_w[NSL * NE];           // switch*fprob
__device__ float  g_c[256];                // commut c[a*16+b]
__device__ double g_acc[8];

// ================= STAGE 1: expmdiff (256) | commut (256) | head (64) ======
struct SmemS1 {
    union {
        struct { float sA[256], sT[256], sS[256], rowsum[16]; int s_sq; double red[128]; } ed;
        struct { double red[256]; } cm;
        struct { float feat[64]; float prob[288]; double lred[16]; } hd;
    } u;
};

__global__ void __launch_bounds__(256) k_stage1(
    const float* __restrict__ ge, const float* __restrict__ z,
    const float* __restrict__ mean, const float* __restrict__ logvar,
    const float* __restrict__ lw, const float* __restrict__ lb,
    const float* __restrict__ gn, float* __restrict__ out)
{
    __shared__ SmemS1 sm;
    int blk = blockIdx.x;
    int t = threadIdx.x;

    if (blk < 256) {
        // ---------- expm(ge[e]) -> diff/invnrm/sparse ----------
        int e = blk;
        int i = t >> 4, j = t & 15;
        float a = ge[e * 256 + t];
        sm.u.ed.sA[t] = fabsf(a);
        __syncthreads();
        if (j == 0) {
            float rs = 0.f;
            #pragma unroll
            for (int k = 0; k < 16; k++) rs += sm.u.ed.sA[i * 16 + k];
            sm.u.ed.rowsum[i] = rs;
        }
        __syncthreads();
        if (t == 0) {
            float mx = 0.f;
            #pragma unroll
            for (int k = 0; k < 16; k++) mx = fmaxf(mx, sm.u.ed.rowsum[k]);
            int s = 0;
            while (mx > 0.25f && s < 60) { mx *= 0.5f; s++; }
            sm.u.ed.s_sq = s;
        }
        __syncthreads();
        int sc = sm.u.ed.s_sq;
        a = ldexpf(a, -sc);
        sm.u.ed.sA[t] = a;
        sm.u.ed.sT[t] = a;
        float pv = ((i == j) ? 1.0f : 0.0f) + a;
        __syncthreads();
        for (int k = 2; k <= 13; k++) {
            float nt = 0.f;
            #pragma unroll
            for (int kk = 0; kk < 16; kk++)
                nt += sm.u.ed.sT[i * 16 + kk] * sm.u.ed.sA[kk * 16 + j];
            nt *= (1.0f / (float)k);
            __syncthreads();
            sm.u.ed.sT[t] = nt;
            pv += nt;
            __syncthreads();
        }
        for (int it = 0; it < sc; it++) {
            sm.u.ed.sS[t] = pv;
            __syncthreads();
            float np = 0.f;
            #pragma unroll
            for (int kk = 0; kk < 16; kk++)
                np += sm.u.ed.sS[i * 16 + kk] * sm.u.ed.sS[kk * 16 + j];
            pv = np;
            __syncthreads();
        }
        sm.u.ed.sS[t] = pv;
        __syncthreads();
        if (t < 128) {
            int b = t;
            float zr[16], dv[16];
            #pragma unroll
            for (int k = 0; k < 16; k++) zr[k] = z[b * 16 + k];
            float n2 = 0.f, mx = 0.f;
            #pragma unroll
            for (int d = 0; d < 16; d++) {
                float m = 0.f;
                #pragma unroll
                for (int k = 0; k < 16; k++) m += zr[k] * sm.u.ed.sS[k * 16 + d];
                float df = zr[d] - m;
                dv[d] = df;
                float q = df * df;
                n2 += q;
                mx = fmaxf(mx, q);
            }
            #pragma unroll
            for (int d = 0; d < 16; d++) g_diff[e * 2048 + b * 16 + d] = dv[d];
            int s = e >> 4, uu = e & 15;
            g_invnrm[s * 2048 + uu * 128 + b] = rsqrtf(n2);
            float sp = n2 - mx;
            sm.u.ed.red[b] = (double)(sp * sp);
        }
        __syncthreads();
        for (int o = 64; o; o >>= 1) {
            if (t < o) sm.u.ed.red[t] += sm.u.ed.red[t + o];
            __syncthreads();
        }
        if (t == 0) atomicAdd(&g_acc[ACC_SPARSE], sm.u.ed.red[0]);
    }
    else if (blk < 512) {
        // ---------- commutator c[a,b] ----------
        int blk2 = blk - 256;
        int a = blk2 >> 4, b = blk2 & 15;
        int i = t >> 4, l = t & 15;
        float r1 = 0.f, r2 = 0.f;
        #pragma unroll
        for (int k = 0; k < 16; k++) {
            float h_bl = ge[4096 * k + b * 16 + l];
            float h_al = ge[4096 * k + a * 16 + l];
            r1 += ge[a * 256 + i * 16 + k] * h_bl;
            r2 += ge[b * 256 + i * 16 + k] * h_al;
        }
        float d = r1 - r2;
        sm.u.cm.red[t] = (double)(d * d);
        __syncthreads();
        for (int o = 128; o; o >>= 1) {
            if (t < o) sm.u.cm.red[t] += sm.u.cm.red[t + o];
            __syncthreads();
        }
        if (t == 0) g_c[a * 16 + b] = (float)(2.0 * sm.u.cm.red[0]);
    }
    else {
        // ---------- linear head (256 threads; 288 outputs) ----------
        int b = blk - 512;
        if (t < 16)      sm.u.hd.feat[t] = mean[b * 16 + t];
        else if (t < 32) sm.u.hd.feat[t] = expf(0.5f * logvar[b * 16 + (t - 16)]);
        else if (t < 48) sm.u.hd.feat[t] = mean[(64 + b) * 16 + (t - 32)];
        else if (t < 64) sm.u.hd.feat[t] = expf(0.5f * mean[(64 + b) * 16 + (t - 48)]);
        __syncthreads();
        {
            // output t, via float4 loads of lw row t
            const float4* lw4 = (const float4*)(lw + t * 64);
            float acc = lb[t];
            #pragma unroll
            for (int k4 = 0; k4 < 16; k4++) {
                float4 v = lw4[k4];
                acc += sm.u.hd.feat[k4 * 4 + 0] * v.x + sm.u.hd.feat[k4 * 4 + 1] * v.y
                     + sm.u.hd.feat[k4 * 4 + 2] * v.z + sm.u.hd.feat[k4 * 4 + 3] * v.w;
            }
            sm.u.hd.prob[t] = acc;
            if (t < 32) {
                int o = 256 + t;
                const float4* lw4b = (const float4*)(lw + o * 64);
                float acc2 = lb[o];
                #pragma unroll
                for (int k4 = 0; k4 < 16; k4++) {
                    float4 v = lw4b[k4];
                    acc2 += sm.u.hd.feat[k4 * 4 + 0] * v.x + sm.u.hd.feat[k4 * 4 + 1] * v.y
                          + sm.u.hd.feat[k4 * 4 + 2] * v.z + sm.u.hd.feat[k4 * 4 + 3] * v.w;
                }
                sm.u.hd.prob[o] = acc2;
            }
        }
        __syncthreads();
        if (t < 16) {
            int s = t;
            float l0 = sm.u.hd.prob[2 * s], l1 = sm.u.hd.prob[2 * s + 1];
            float m = fmaxf(l0, l1);
            float e0 = expf(l0 - m), e1 = expf(l1 - m);
            float inv = 1.0f / (e0 + e1);
            float p0 = e0 * inv, p1 = e1 * inv;
            float m2 = fmaxf(p0, p1);
            float lse = m2 + logf(expf(p0 - m2) + expf(p1 - m2));
            float zd = z[b * 16 + s] - z[(64 + b) * 16 + s];
            int tgt = (fabsf(zd) > 0.2f) ? 1 : 0;
            float ls = (tgt ? p1 : p0) - lse;
            sm.u.hd.lred[s] = (double)(-ls);
            int r = b * 16 + s;
            float g0 = gn[2 * r], g1 = gn[2 * r + 1];
            float x0 = (l0 + g0) * 10000.0f, x1 = (l1 + g1) * 10000.0f;
            float a1 = 1.0f / (1.0f + expf(x0 - x1));
            float a0 = 1.0f / (1.0f + expf(x1 - x0));
            float sw = ((a0 >= 0.5f) || (a1 > 0.5f)) ? a1 : 0.0f;
            out[OUT_ATTN + b * 272 + s] = sw;
            float f[16];
            float fm = -3.0e38f;
            #pragma unroll
            for (int u = 0; u < 16; u++) { f[u] = sm.u.hd.prob[32 + s * 16 + u]; fm = fmaxf(fm, f[u]); }
            float sum = 0.f;
            #pragma unroll
            for (int u = 0; u < 16; u++) { f[u] = expf(f[u] - fm); sum += f[u]; }
            float invs = 1.0f / sum;
            #pragma unroll
            for (int u = 0; u < 16; u++) {
                float fp = f[u] * invs;
                out[OUT_ATTN + b * 272 + 16 + s * 16 + u] = fp;
                g_w[b * 256 + s * 16 + u] = sw * fp;
            }
        }
        __syncthreads();
        if (t == 0) {
            double sl = 0.0;
            for (int s = 0; s < 16; s++) sl += sm.u.hd.lred[s];
            atomicAdd(&g_acc[ACC_SECTOR], sl);
        }
    }
}

// ===== STAGE 2: parallel (1088) | orth (120) | syms2 (16) =====
struct SmemS2 {
    union {
        struct { float Am[128][18]; float Bt[16][132]; float im[128], inr[128]; double wred[8]; } pa;
        struct { float A[128][17]; float B[128][17]; float ia[128], ib[128]; double wred[8]; } ot;
        struct { float geS[16][256]; float wsh[64][16]; } sy;
    } u;
};

__global__ void __launch_bounds__(256, 2) k_stage2(
    const int* __restrict__ sec_idx, const float* __restrict__ ge, float* __restrict__ out)
{
    __shared__ SmemS2 sm;
    int blk = blockIdx.x;
    int tid = threadIdx.x;

    if (blk < 1088) {
        // ---------- parallel: sector s = blk/68, bx = blk%68; 2 tiles ----------
        int s = blk / 68, bx = blk % 68;
        int tx = tid & 15, ty = tid >> 4;
        const float* base = g_diff + s * 32768;
        double total = 0.0;
        unsigned long long E2;
        PACK2(E2, 1e-9f, 1e-9f);

        #pragma unroll 1
        for (int half = 0; half < 2; half++) {
            int p = bx + half * 68;
            int ti = 0, rem = p;
            while (rem >= 16 - ti) { rem -= 16 - ti; ti++; }
            int tj = ti + rem;

            if (half) __syncthreads();
            for (int idx = tid; idx < 2048; idx += 256) {
                int r = idx >> 4, d = idx & 15;
                sm.u.pa.Am[r][d] = base[(ti * 128 + r) * 16 + d];
                sm.u.pa.Bt[d][r] = base[(tj * 128 + r) * 16 + d];
            }
            if (tid < 128) {
                sm.u.pa.im[tid]  = g_invnrm[s * 2048 + ti * 128 + tid];
                sm.u.pa.inr[tid] = g_invnrm[s * 2048 + tj * 128 + tid];
            }
            __syncthreads();

            unsigned long long acc2[8][4];
            #pragma unroll
            for (int i = 0; i < 8; i++)
                #pragma unroll
                for (int q = 0; q < 4; q++) acc2[i][q] = 0ULL;

            #pragma unroll 4
            for (int d = 0; d < 16; d++) {
                unsigned long long a2[8], b2[4];
                #pragma unroll
                for (int i = 0; i < 8; i++) {
                    float av = sm.u.pa.Am[ty * 8 + i][d];
                    PACK2(a2[i], av, av);
                }
                #pragma unroll
                for (int q = 0; q < 4; q++)
                    b2[q] = *(const unsigned long long*)&sm.u.pa.Bt[d][2 * tx + 32 * q];
                #pragma unroll
                for (int i = 0; i < 8; i++)
                    #pragma unroll
                    for (int q = 0; q < 4; q++)
                        FMA2(acc2[i][q], a2[i], b2[q]);
            }

            unsigned long long inr2[4];
            #pragma unroll
            for (int q = 0; q < 4; q++)
                inr2[q] = *(const unsigned long long*)&sm.u.pa.inr[2 * tx + 32 * q];

            float sum = 0.f;
            if (ti != tj) {
                #pragma unroll
                for (int i = 0; i < 8; i++) {
                    float pi = sm.u.pa.im[ty * 8 + i];
                    unsigned long long pi2;
                    PACK2(pi2, pi, pi);
                    unsigned long long t2[4];
                    #pragma unroll
                    for (int q = 0; q < 4; q++) {
                        unsigned long long uu;
                        MUL2(uu, acc2[i][q], pi2);
                        MUL2(uu, uu, inr2[q]);
                        FMA2SQ(t2[q], uu, E2);
                    }
                    unsigned long long w1, w2;
                    MUL2(w1, t2[0], t2[1]);
                    MUL2(w2, t2[2], t2[3]);
                    float x0, x1, y0, y1;
                    UNPACK2(x0, x1, w1);
                    UNPACK2(y0, y1, w2);
                    sum -= __logf(x0 * x1) + __logf(y0 * y1);
                }
                total += 2.0 * (double)sum;
            } else {
                #pragma unroll
                for (int i = 0; i < 8; i++) {
                    int r = ty * 8 + i;
                    float pi = sm.u.pa.im[r];
                    #pragma unroll
                    for (int q = 0; q < 4; q++) {
                        float d0, d1;
                        UNPACK2(d0, d1, acc2[i][q]);
                        int c0 = 2 * tx + 32 * q, c1 = c0 + 1;
                        float r0 = d0 * pi * sm.u.pa.inr[c0];
                        float r1 = d1 * pi * sm.u.pa.inr[c1];
                        float v0 = -__logf(fmaf(r0, r0, 1e-9f));
                        float v1 = -__logf(fmaf(r1, r1, 1e-9f));
                        float w0 = (c0 > r) ? 2.0f : ((c0 == r) ? 1.0f : 0.0f);
                        float w1w = (c1 > r) ? 2.0f : ((c1 == r) ? 1.0f : 0.0f);
                        sum += w0 * v0 + w1w * v1;
                    }
                }
                total += (double)sum;
            }
        }

        #pragma unroll
        for (int o = 16; o; o >>= 1) total += __shfl_xor_sync(0xffffffffu, total, o);
        if ((tid & 31) == 0) sm.u.pa.wred[tid >> 5] = total;
        __syncthreads();
        if (tid < 32) {
            double v = (tid < 8) ? sm.u.pa.wred[tid] : 0.0;
            #pragma unroll
            for (int o = 4; o; o >>= 1) v += __shfl_xor_sync(0xffffffffu, v, o);
            if (tid == 0) atomicAdd(&g_acc[ACC_PAR], v);
        }
    }
    else if (blk < 1208) {
        // ---------- orth pair ----------
        int bx = blk - 1088;
        int s1 = 0, rem = bx;
        while (rem >= 15 - s1) { rem -= 15 - s1; s1++; }
        int s2 = s1 + 1 + rem;
        int tx = tid & 15, ty = tid >> 4;
        int u1 = sec_idx[s1], u2 = sec_idx[s2];
        const float* pa = g_diff + s1 * 32768 + u1 * 2048;
        const float* pb = g_diff + s2 * 32768 + u2 * 2048;
        for (int idx = tid; idx < 2048; idx += 256) {
            int r = idx >> 4, d = idx & 15;
            sm.u.ot.A[r][d] = pa[r * 16 + d];
            sm.u.ot.B[r][d] = pb[r * 16 + d];
        }
        if (tid < 128) {
            sm.u.ot.ia[tid] = g_invnrm[s1 * 2048 + u1 * 128 + tid];
            sm.u.ot.ib[tid] = g_invnrm[s2 * 2048 + u2 * 128 + tid];
        }
        __syncthreads();

        float acc[8][8];
        #pragma unroll
        for (int i = 0; i < 8; i++)
            #pragma unroll
            for (int j = 0; j < 8; j++) acc[i][j] = 0.f;

        #pragma unroll
        for (int d = 0; d < 16; d++) {
            float af[8], bf[8];
            #pragma unroll
            for (int i = 0; i < 8; i++) af[i] = sm.u.ot.A[ty * 8 + i][d];
            #pragma unroll
            for (int j = 0; j < 8; j++) bf[j] = sm.u.ot.B[tx + 16 * j][d];
            #pragma unroll
            for (int i = 0; i < 8; i++)
                #pragma unroll
                for (int j = 0; j < 8; j++)
                    acc[i][j] = fmaf(af[i], bf[j], acc[i][j]);
        }

        float sum = 0.f;
        #pragma unroll
        for (int i = 0; i < 8; i++) {
            float ia = sm.u.ot.ia[ty * 8 + i];
            #pragma unroll
            for (int j = 0; j < 8; j++) {
                float ratio = acc[i][j] * ia * sm.u.ot.ib[tx + 16 * j];
                sum += ratio * ratio;
            }
        }
        double total = (double)sum;
        #pragma unroll
        for (int o = 16; o; o >>= 1) total += __shfl_xor_sync(0xffffffffu, total, o);
        if ((tid & 31) == 0) sm.u.ot.wred[tid >> 5] = total;
        __syncthreads();
        if (tid < 32) {
            double v = (tid < 8) ? sm.u.ot.wred[tid] : 0.0;
            #pragma unroll
            for (int o = 4; o; o >>= 1) v += __shfl_xor_sync(0xffffffffu, v, o);
            if (tid == 0) atomicAdd(&g_acc[ACC_ORTH], v);
        }
    }
    else {
        // ---------- sub_syms per sector ----------
        int s = blk - 1208;
        int t = tid;
        #pragma unroll
        for (int u = 0; u < 16; u++)
            sm.u.sy.geS[u][t] = ge[(s * 16 + u) * 256 + t];
        for (int idx = t; idx < 64 * 16; idx += 256)
            sm.u.sy.wsh[idx >> 4][idx & 15] = g_w[(idx >> 4) * 256 + s * 16 + (idx & 15)];
        __syncthreads();
        #pragma unroll 4
        for (int b = 0; b < 64; b++) {
            float sub = 0.f;
            #pragma unroll
            for (int u = 0; u < 16; u++)
                sub = fmaf(sm.u.sy.wsh[b][u], sm.u.sy.geS[u][t], sub);
            out[OUT_SUB + b * 4096 + s * 256 + t] = sub;
        }
    }
}

// ===== STAGE 3: expm(±S) + fused tz; 128 blocks =====
__global__ void __launch_bounds__(256) k_stage3(const float* __restrict__ z, float* __restrict__ out)
{
    __shared__ float sA[256];
    __shared__ float sT[256];
    __shared__ float sP[256];
    __shared__ float rowsum[16];
    __shared__ int s_sq;
    int t = threadIdx.x;
    int i = t >> 4, j = t & 15;
    int blk = blockIdx.x;
    int m = blk & 63;
    int invm = blk >> 6;
    float sign = invm ? -1.0f : 1.0f;

    float Sv = 0.f;
    #pragma unroll
    for (int s = 0; s < 16; s++)
        Sv += out[OUT_SUB + m * 4096 + s * 256 + t];
    float a = sign * Sv;
    sA[t] = fabsf(a);
    __syncthreads();
    if (j == 0) {
        float rs = 0.f;
        #pragma unroll
        for (int k = 0; k < 16; k++) rs += sA[i * 16 + k];
        rowsum[i] = rs;
    }
    __syncthreads();
    if (t == 0) {
        float mx = 0.f;
        #pragma unroll
        for (int k = 0; k < 16; k++) mx = fmaxf(mx, rowsum[k]);
        int s = 0;
        while (mx > 0.25f && s < 60) { mx *= 0.5f; s++; }
        s_sq = s;
    }
    __syncthreads();
    int s = s_sq;
    a = ldexpf(a, -s);
    sA[t] = a;
    sT[t] = a;
    float p = ((i == j) ? 1.0f : 0.0f) + a;
    __syncthreads();
    for (int k = 2; k <= 13; k++) {
        float nt = 0.f;
        #pragma unroll
        for (int kk = 0; kk < 16; kk++)
            nt += sT[i * 16 + kk] * sA[kk * 16 + j];
        nt *= (1.0f / (float)k);
        __syncthreads();
        sT[t] = nt;
        p += nt;
        __syncthreads();
    }
    for (int it = 0; it < s; it++) {
        sP[t] = p;
        __syncthreads();
        float np = 0.f;
        #pragma unroll
        for (int kk = 0; kk < 16; kk++)
            np += sP[i * 16 + kk] * sP[kk * 16 + j];
        p = np;
        __syncthreads();
    }
    sP[t] = p;               // final expm in shared
    if (!invm) out[OUT_FWD + m * 256 + t] = p;
    __syncthreads();

    // fused tz half: tz1 for fwd blocks, tz2 for inv blocks
    if (t < 16) {
        int d = t;
        float v = 0.f, dd;
        if (!invm) {
            #pragma unroll
            for (int k = 0; k < 16; k++)
                v += z[m * 16 + k] * sP[k * 16 + d];
            out[OUT_TZ1 + m * 16 + d] = v;
            dd = v - z[(64 + m) * 16 + d];   // tz1 - z2
        } else {
            #pragma unroll
            for (int k = 0; k < 16; k++)
                v += z[(64 + m) * 16 + k] * sP[k * 16 + d];
            out[OUT_TZ2 + m * 16 + d] = v;
            dd = v - z[m * 16 + d];          // tz2 - z1
        }
        float term = dd * dd;
        #pragma unroll
        for (int o = 8; o; o >>= 1) term += __shfl_xor_sync(0xffffu, term, o);
        if (t == 0) atomicAdd(&g_acc[ACC_EQ], (double)term);
    }
}

// ===== STAGE 4: final scalar writes =====
__global__ void k_final(float* __restrict__ out)
{
    if (threadIdx.x == 0) {
        out[OUT_PAR]    = (float)(g_acc[ACC_PAR] / (16.0 * 2048.0 * 2048.0));
        out[OUT_ORTH]   = (float)(2.0 * g_acc[ACC_ORTH] / (2048.0 * 2048.0));
        out[OUT_SPARSE] = (float)(g_acc[ACC_SPARSE] / 32768.0);
        out[OUT_SECTOR] = (float)(g_acc[ACC_SECTOR] / 64.0);
        out[OUT_EQ]     = (float)(g_acc[ACC_EQ] / 1024.0);
        double cm = 0.0;
        int p = 0;
        for (int a = 0; a < 16; a++)
            for (int b = a + 1; b < 16; b++) {
                cm += (double)g_c[a * 16 + b] * (double)(120 - p);
                p++;
            }
        out[OUT_COMMUT] = (float)(cm / (4096.0 * 4096.0));
    }
}

extern "C" void kernel_launch(void* const* d_in, const int* in_sizes, int n_in,
                              void* d_out, int out_size)
{
    // resolve inputs by element count (robust to metadata ordering)
    int ige = -1, ilw = -1, ilb = -1, isx = -1;
    int i2048[4]; int n2 = 0;
    for (int i = 0; i < n_in; i++) {
        int sz = in_sizes[i];
        if (sz == 65536) ige = i;
        else if (sz == 18432) ilw = i;
        else if (sz == 288) ilb = i;
        else if (sz == 16) isx = i;
        else if (sz == 2048 && n2 < 4) i2048[n2++] = i;
    }
    int imean, ilogvar, iz, ign;
    if (ige == 0) {
        ign = i2048[0]; iz = i2048[1]; ilogvar = i2048[2]; imean = i2048[3];
    } else {
        imean = i2048[0]; ilogvar = i2048[1]; iz = i2048[2]; ign = i2048[3];
    }

    const float* mean   = (const float*)d_in[imean];
    const float* logvar = (const float*)d_in[ilogvar];
    const float* z      = (const float*)d_in[iz];
    const float* ge     = (const float*)d_in[ige];
    const float* lw     = (const float*)d_in[ilw];
    const float* lb     = (const float*)d_in[ilb];
    const float* gn     = (const float*)d_in[ign];
    const int*   sidx   = (const int*)d_in[isx];
    float* out = (float*)d_out;

    static void* accPtr = nullptr;
    if (!accPtr) cudaGetSymbolAddress(&accPtr, g_acc);

    cudaMemsetAsync(accPtr, 0, 8 * sizeof(double), 0);
    k_stage1<<<576, 256>>>(ge, z, mean, logvar, lw, lb, gn, out);
    k_stage2<<<1224, 256>>>(sidx, ge, out);
    k_stage3<<<128, 256>>>(z, out);
    k_final<<<1, 32>>>(out);
}

// round 17
// speedup vs baseline: 1.3982x; 1.1357x over previous
#include <cuda_runtime.h>
#include <math.h>

#define DIMN 16
#define NSEC 16
#define NSUB 16
#define NE   256
#define NB   128
#define NSL  64

// ---- output layout (flattened tuple, fp32) ----
#define OUT_TZ1    0
#define OUT_TZ2    1024
#define OUT_FWD    2048
#define OUT_EQ     18432
#define OUT_ATTN   18433
#define OUT_ORTH   35841
#define OUT_PAR    35842
#define OUT_COMMUT 35843
#define OUT_SPARSE 35844
#define OUT_SECTOR 35845
#define OUT_SUB    35846

// accumulators
#define ACC_PAR    0
#define ACC_ORTH   1
#define ACC_SPARSE 2
#define ACC_SECTOR 3
#define ACC_EQ     4
#define ACC_COMMUT 5

// ---- packed f32x2 ops (sm_103a) ----
#define PACK2(o, x, y)   asm("mov.b64 %0, {%1, %2};" : "=l"(o) : "f"(x), "f"(y))
#define UNPACK2(x, y, v) asm("mov.b64 {%0, %1}, %2;" : "=f"(x), "=f"(y) : "l"(v))
#define FMA2(d, a, b)    asm("fma.rn.f32x2 %0, %1, %2, %0;" : "+l"(d) : "l"(a), "l"(b))
#define FMA2SQ(d, a, c)  asm("fma.rn.f32x2 %0, %1, %1, %2;" : "=l"(d) : "l"(a), "l"(c))
#define MUL2(d, a, b)    asm("mul.rn.f32x2 %0, %1, %2;" : "=l"(d) : "l"(a), "l"(b))

// ---- scratch (__device__ globals; referenced ONLY from device code) ----
__device__ float  g_diff[NE * NB * DIMN];  // [e][b][d]
__device__ float  g_invnrm[NSEC * 2048];   // [s][m], m = u*128 + b
__device__ float  g_w[NSL * NE];           // switch*fprob
__device__ double g_acc[8];
__device__ unsigned int g_done;

// ================= STAGE 1: expmdiff (256) | commut (120) | head (64) ======
struct SmemS1 {
    union {
        struct { float sA[256], sT[256], sS[256], rowsum[16]; int s_sq; double red[128]; } ed;
        struct { double red[256]; } cm;
        struct { float feat[64]; float prob[288]; double lred[16]; } hd;
    } u;
};

__global__ void __launch_bounds__(256) k_stage1(
    const float* __restrict__ ge, const float* __restrict__ z,
    const float* __restrict__ mean, const float* __restrict__ logvar,
    const float* __restrict__ lw, const float* __restrict__ lb,
    const float* __restrict__ gn, float* __restrict__ out)
{
    __shared__ SmemS1 sm;
    int blk = blockIdx.x;
    int t = threadIdx.x;
    if (blk == 0 && t == 0) g_done = 0;   // reset completion counter each launch

    if (blk < 256) {
        // ---------- expm(ge[e]) -> diff/invnrm/sparse ----------
        int e = blk;
        int i = t >> 4, j = t & 15;
        float a = ge[e * 256 + t];
        sm.u.ed.sA[t] = fabsf(a);
        __syncthreads();
        if (j == 0) {
            float rs = 0.f;
            #pragma unroll
            for (int k = 0; k < 16; k++) rs += sm.u.ed.sA[i * 16 + k];
            sm.u.ed.rowsum[i] = rs;
        }
        __syncthreads();
        if (t == 0) {
            float mx = 0.f;
            #pragma unroll
            for (int k = 0; k < 16; k++) mx = fmaxf(mx, sm.u.ed.rowsum[k]);
            int s = 0;
            while (mx > 0.25f && s < 60) { mx *= 0.5f; s++; }
            sm.u.ed.s_sq = s;
        }
        __syncthreads();
        int sc = sm.u.ed.s_sq;
        a = ldexpf(a, -sc);
        sm.u.ed.sA[t] = a;
        sm.u.ed.sT[t] = a;
        float pv = ((i == j) ? 1.0f : 0.0f) + a;
        __syncthreads();
        for (int k = 2; k <= 7; k++) {
            float nt = 0.f;
            #pragma unroll
            for (int kk = 0; kk < 16; kk++)
                nt += sm.u.ed.sT[i * 16 + kk] * sm.u.ed.sA[kk * 16 + j];
            nt *= (1.0f / (float)k);
            __syncthreads();
            sm.u.ed.sT[t] = nt;
            pv += nt;
            __syncthreads();
        }
        for (int it = 0; it < sc; it++) {
            sm.u.ed.sS[t] = pv;
            __syncthreads();
            float np = 0.f;
            #pragma unroll
            for (int kk = 0; kk < 16; kk++)
                np += sm.u.ed.sS[i * 16 + kk] * sm.u.ed.sS[kk * 16 + j];
            pv = np;
            __syncthreads();
        }
        sm.u.ed.sS[t] = pv;
        __syncthreads();
        if (t < 128) {
            int b = t;
            float zr[16], dv[16];
            #pragma unroll
            for (int k = 0; k < 16; k++) zr[k] = z[b * 16 + k];
            float n2 = 0.f, mx = 0.f;
            #pragma unroll
            for (int d = 0; d < 16; d++) {
                float m = 0.f;
                #pragma unroll
                for (int k = 0; k < 16; k++) m += zr[k] * sm.u.ed.sS[k * 16 + d];
                float df = zr[d] - m;
                dv[d] = df;
                float q = df * df;
                n2 += q;
                mx = fmaxf(mx, q);
            }
            #pragma unroll
            for (int d = 0; d < 16; d++) g_diff[e * 2048 + b * 16 + d] = dv[d];
            int s = e >> 4, uu = e & 15;
            g_invnrm[s * 2048 + uu * 128 + b] = rsqrtf(n2);
            float sp = n2 - mx;
            sm.u.ed.red[b] = (double)(sp * sp);
        }
        __syncthreads();
        for (int o = 64; o; o >>= 1) {
            if (t < o) sm.u.ed.red[t] += sm.u.ed.red[t + o];
            __syncthreads();
        }
        if (t == 0) atomicAdd(&g_acc[ACC_SPARSE], sm.u.ed.red[0]);
    }
    else if (blk < 376) {
        // ---------- commutator, pair (a<b), weighted in-block ----------
        int p = blk - 256;                  // triu linear index 0..119
        int a = 0, rem = p;
        while (rem >= 15 - a) { rem -= 15 - a; a++; }
        int b = a + 1 + rem;
        float weight = (float)(120 - p);
        int i = t >> 4, l = t & 15;
        float r1 = 0.f, r2 = 0.f;
        #pragma unroll
        for (int k = 0; k < 16; k++) {
            float h_bl = ge[4096 * k + b * 16 + l];
            float h_al = ge[4096 * k + a * 16 + l];
            r1 += ge[a * 256 + i * 16 + k] * h_bl;
            r2 += ge[b * 256 + i * 16 + k] * h_al;
        }
        float d = r1 - r2;
        sm.u.cm.red[t] = (double)(d * d);
        __syncthreads();
        for (int o = 128; o; o >>= 1) {
            if (t < o) sm.u.cm.red[t] += sm.u.cm.red[t + o];
            __syncthreads();
        }
        if (t == 0) atomicAdd(&g_acc[ACC_COMMUT], 2.0 * (double)weight * sm.u.cm.red[0]);
    }
    else {
        // ---------- linear head (256 threads; 288 outputs) ----------
        int b = blk - 376;
        if (t < 16)      sm.u.hd.feat[t] = mean[b * 16 + t];
        else if (t < 32) sm.u.hd.feat[t] = expf(0.5f * logvar[b * 16 + (t - 16)]);
        else if (t < 48) sm.u.hd.feat[t] = mean[(64 + b) * 16 + (t - 32)];
        else if (t < 64) sm.u.hd.feat[t] = expf(0.5f * mean[(64 + b) * 16 + (t - 48)]);
        __syncthreads();
        {
            const float4* lw4 = (const float4*)(lw + t * 64);
            float acc = lb[t];
            #pragma unroll
            for (int k4 = 0; k4 < 16; k4++) {
                float4 v = lw4[k4];
                acc += sm.u.hd.feat[k4 * 4 + 0] * v.x + sm.u.hd.feat[k4 * 4 + 1] * v.y
                     + sm.u.hd.feat[k4 * 4 + 2] * v.z + sm.u.hd.feat[k4 * 4 + 3] * v.w;
            }
            sm.u.hd.prob[t] = acc;
            if (t < 32) {
                int o = 256 + t;
                const float4* lw4b = (const float4*)(lw + o * 64);
                float acc2 = lb[o];
                #pragma unroll
                for (int k4 = 0; k4 < 16; k4++) {
                    float4 v = lw4b[k4];
                    acc2 += sm.u.hd.feat[k4 * 4 + 0] * v.x + sm.u.hd.feat[k4 * 4 + 1] * v.y
                          + sm.u.hd.feat[k4 * 4 + 2] * v.z + sm.u.hd.feat[k4 * 4 + 3] * v.w;
                }
                sm.u.hd.prob[o] = acc2;
            }
        }
        __syncthreads();
        if (t < 16) {
            int s = t;
            float l0 = sm.u.hd.prob[2 * s], l1 = sm.u.hd.prob[2 * s + 1];
            float m = fmaxf(l0, l1);
            float e0 = expf(l0 - m), e1 = expf(l1 - m);
            float inv = 1.0f / (e0 + e1);
            float p0 = e0 * inv, p1 = e1 * inv;
            float m2 = fmaxf(p0, p1);
            float lse = m2 + logf(expf(p0 - m2) + expf(p1 - m2));
            float zd = z[b * 16 + s] - z[(64 + b) * 16 + s];
            int tgt = (fabsf(zd) > 0.2f) ? 1 : 0;
            float ls = (tgt ? p1 : p0) - lse;
            sm.u.hd.lred[s] = (double)(-ls);
            int r = b * 16 + s;
            float g0 = gn[2 * r], g1 = gn[2 * r + 1];
            float x0 = (l0 + g0) * 10000.0f, x1 = (l1 + g1) * 10000.0f;
            float a1 = 1.0f / (1.0f + expf(x0 - x1));
            float a0 = 1.0f / (1.0f + expf(x1 - x0));
            float sw = ((a0 >= 0.5f) || (a1 > 0.5f)) ? a1 : 0.0f;
            out[OUT_ATTN + b * 272 + s] = sw;
            float f[16];
            float fm = -3.0e38f;
            #pragma unroll
            for (int u = 0; u < 16; u++) { f[u] = sm.u.hd.prob[32 + s * 16 + u]; fm = fmaxf(fm, f[u]); }
            float sum = 0.f;
            #pragma unroll
            for (int u = 0; u < 16; u++) { f[u] = expf(f[u] - fm); sum += f[u]; }
            float invs = 1.0f / sum;
            #pragma unroll
            for (int u = 0; u < 16; u++) {
                float fp = f[u] * invs;
                out[OUT_ATTN + b * 272 + 16 + s * 16 + u] = fp;
                g_w[b * 256 + s * 16 + u] = sw * fp;
            }
        }
        __syncthreads();
        if (t == 0) {
            double sl = 0.0;
            for (int s = 0; s < 16; s++) sl += sm.u.hd.lred[s];
            atomicAdd(&g_acc[ACC_SECTOR], sl);
        }
    }
}

// ===== STAGE 2: parallel (1088) | orth (120) | syms2 (16) =====
struct SmemS2 {
    union {
        struct { float Am[128][18]; float Bt[16][132]; float im[128], inr[128]; double wred[8]; } pa;
        struct { float A[128][17]; float B[128][17]; float ia[128], ib[128]; double wred[8]; } ot;
        struct { float geS[16][256]; float wsh[64][16]; } sy;
    } u;
};

__global__ void __launch_bounds__(256, 2) k_stage2(
    const int* __restrict__ sec_idx, const float* __restrict__ ge, float* __restrict__ out)
{
    __shared__ SmemS2 sm;
    int blk = blockIdx.x;
    int tid = threadIdx.x;

    if (blk < 1088) {
        // ---------- parallel: sector s = blk/68, bx = blk%68; 2 tiles ----------
        int s = blk / 68, bx = blk % 68;
        int tx = tid & 15, ty = tid >> 4;
        const float* base = g_diff + s * 32768;
        double total = 0.0;
        unsigned long long E2;
        PACK2(E2, 1e-9f, 1e-9f);

        #pragma unroll 1
        for (int half = 0; half < 2; half++) {
            int p = bx + half * 68;
            int ti = 0, rem = p;
            while (rem >= 16 - ti) { rem -= 16 - ti; ti++; }
            int tj = ti + rem;

            if (half) __syncthreads();
            for (int idx = tid; idx < 2048; idx += 256) {
                int r = idx >> 4, d = idx & 15;
                sm.u.pa.Am[r][d] = base[(ti * 128 + r) * 16 + d];
                sm.u.pa.Bt[d][r] = base[(tj * 128 + r) * 16 + d];
            }
            if (tid < 128) {
                sm.u.pa.im[tid]  = g_invnrm[s * 2048 + ti * 128 + tid];
                sm.u.pa.inr[tid] = g_invnrm[s * 2048 + tj * 128 + tid];
            }
            __syncthreads();

            unsigned long long acc2[8][4];
            #pragma unroll
            for (int i = 0; i < 8; i++)
                #pragma unroll
                for (int q = 0; q < 4; q++) acc2[i][q] = 0ULL;

            #pragma unroll 4
            for (int d = 0; d < 16; d++) {
                unsigned long long a2[8], b2[4];
                #pragma unroll
                for (int i = 0; i < 8; i++) {
                    float av = sm.u.pa.Am[ty * 8 + i][d];
                    PACK2(a2[i], av, av);
                }
                #pragma unroll
                for (int q = 0; q < 4; q++)
                    b2[q] = *(const unsigned long long*)&sm.u.pa.Bt[d][2 * tx + 32 * q];
                #pragma unroll
                for (int i = 0; i < 8; i++)
                    #pragma unroll
                    for (int q = 0; q < 4; q++)
                        FMA2(acc2[i][q], a2[i], b2[q]);
            }

            unsigned long long inr2[4];
            #pragma unroll
            for (int q = 0; q < 4; q++)
                inr2[q] = *(const unsigned long long*)&sm.u.pa.inr[2 * tx + 32 * q];

            float sum = 0.f;
            if (ti != tj) {
                #pragma unroll
                for (int i = 0; i < 8; i++) {
                    float pi = sm.u.pa.im[ty * 8 + i];
                    unsigned long long pi2;
                    PACK2(pi2, pi, pi);
                    unsigned long long t2[4];
                    #pragma unroll
                    for (int q = 0; q < 4; q++) {
                        unsigned long long uu;
                        MUL2(uu, acc2[i][q], pi2);
                        MUL2(uu, uu, inr2[q]);
                        FMA2SQ(t2[q], uu, E2);
                    }
                    unsigned long long w1, w2;
                    MUL2(w1, t2[0], t2[1]);
                    MUL2(w2, t2[2], t2[3]);
                    float x0, x1, y0, y1;
                    UNPACK2(x0, x1, w1);
                    UNPACK2(y0, y1, w2);
                    sum -= __logf(x0 * x1) + __logf(y0 * y1);
                }
                total += 2.0 * (double)sum;
            } else {
                #pragma unroll
                for (int i = 0; i < 8; i++) {
                    int r = ty * 8 + i;
                    float pi = sm.u.pa.im[r];
                    #pragma unroll
                    for (int q = 0; q < 4; q++) {
                        float d0, d1;
                        UNPACK2(d0, d1, acc2[i][q]);
                        int c0 = 2 * tx + 32 * q, c1 = c0 + 1;
                        float r0 = d0 * pi * sm.u.pa.inr[c0];
                        float r1 = d1 * pi * sm.u.pa.inr[c1];
                        float v0 = -__logf(fmaf(r0, r0, 1e-9f));
                        float v1 = -__logf(fmaf(r1, r1, 1e-9f));
                        float w0 = (c0 > r) ? 2.0f : ((c0 == r) ? 1.0f : 0.0f);
                        float w1w = (c1 > r) ? 2.0f : ((c1 == r) ? 1.0f : 0.0f);
                        sum += w0 * v0 + w1w * v1;
                    }
                }
                total += (double)sum;
            }
        }

        #pragma unroll
        for (int o = 16; o; o >>= 1) total += __shfl_xor_sync(0xffffffffu, total, o);
        if ((tid & 31) == 0) sm.u.pa.wred[tid >> 5] = total;
        __syncthreads();
        if (tid < 32) {
            double v = (tid < 8) ? sm.u.pa.wred[tid] : 0.0;
            #pragma unroll
            for (int o = 4; o; o >>= 1) v += __shfl_xor_sync(0xffffffffu, v, o);
            if (tid == 0) atomicAdd(&g_acc[ACC_PAR], v);
        }
    }
    else if (blk < 1208) {
        // ---------- orth pair ----------
        int bx = blk - 1088;
        int s1 = 0, rem = bx;
        while (rem >= 15 - s1) { rem -= 15 - s1; s1++; }
        int s2 = s1 + 1 + rem;
        int tx = tid & 15, ty = tid >> 4;
        int u1 = sec_idx[s1], u2 = sec_idx[s2];
        const float* pa = g_diff + s1 * 32768 + u1 * 2048;
        const float* pb = g_diff + s2 * 32768 + u2 * 2048;
        for (int idx = tid; idx < 2048; idx += 256) {
            int r = idx >> 4, d = idx & 15;
            sm.u.ot.A[r][d] = pa[r * 16 + d];
            sm.u.ot.B[r][d] = pb[r * 16 + d];
        }
        if (tid < 128) {
            sm.u.ot.ia[tid] = g_invnrm[s1 * 2048 + u1 * 128 + tid];
            sm.u.ot.ib[tid] = g_invnrm[s2 * 2048 + u2 * 128 + tid];
        }
        __syncthreads();

        float acc[8][8];
        #pragma unroll
        for (int i = 0; i < 8; i++)
            #pragma unroll
            for (int j = 0; j < 8; j++) acc[i][j] = 0.f;

        #pragma unroll
        for (int d = 0; d < 16; d++) {
            float af[8], bf[8];
            #pragma unroll
            for (int i = 0; i < 8; i++) af[i] = sm.u.ot.A[ty * 8 + i][d];
            #pragma unroll
            for (int j = 0; j < 8; j++) bf[j] = sm.u.ot.B[tx + 16 * j][d];
            #pragma unroll
            for (int i = 0; i < 8; i++)
                #pragma unroll
                for (int j = 0; j < 8; j++)
                    acc[i][j] = fmaf(af[i], bf[j], acc[i][j]);
        }

        float sum = 0.f;
        #pragma unroll
        for (int i = 0; i < 8; i++) {
            float ia = sm.u.ot.ia[ty * 8 + i];
            #pragma unroll
            for (int j = 0; j < 8; j++) {
                float ratio = acc[i][j] * ia * sm.u.ot.ib[tx + 16 * j];
                sum += ratio * ratio;
            }
        }
        double total = (double)sum;
        #pragma unroll
        for (int o = 16; o; o >>= 1) total += __shfl_xor_sync(0xffffffffu, total, o);
        if ((tid & 31) == 0) sm.u.ot.wred[tid >> 5] = total;
        __syncthreads();
        if (tid < 32) {
            double v = (tid < 8) ? sm.u.ot.wred[tid] : 0.0;
            #pragma unroll
            for (int o = 4; o; o >>= 1) v += __shfl_xor_sync(0xffffffffu, v, o);
            if (tid == 0) atomicAdd(&g_acc[ACC_ORTH], v);
        }
    }
    else {
        // ---------- sub_syms per sector ----------
        int s = blk - 1208;
        int t = tid;
        #pragma unroll
        for (int u = 0; u < 16; u++)
            sm.u.sy.geS[u][t] = ge[(s * 16 + u) * 256 + t];
        for (int idx = t; idx < 64 * 16; idx += 256)
            sm.u.sy.wsh[idx >> 4][idx & 15] = g_w[(idx >> 4) * 256 + s * 16 + (idx & 15)];
        __syncthreads();
        #pragma unroll 4
        for (int b = 0; b < 64; b++) {
            float sub = 0.f;
            #pragma unroll
            for (int u = 0; u < 16; u++)
                sub = fmaf(sm.u.sy.wsh[b][u], sm.u.sy.geS[u][t], sub);
            out[OUT_SUB + b * 4096 + s * 256 + t] = sub;
        }
    }
}

// ===== STAGE 3: expm(±S) + fused tz; last block writes final scalars =====
__global__ void __launch_bounds__(256) k_stage3(const float* __restrict__ z, float* __restrict__ out)
{
    __shared__ float sA[256];
    __shared__ float sT[256];
    __shared__ float sP[256];
    __shared__ float rowsum[16];
    __shared__ int s_sq;
    int t = threadIdx.x;
    int i = t >> 4, j = t & 15;
    int blk = blockIdx.x;
    int m = blk & 63;
    int invm = blk >> 6;
    float sign = invm ? -1.0f : 1.0f;

    float Sv = 0.f;
    #pragma unroll
    for (int s = 0; s < 16; s++)
        Sv += out[OUT_SUB + m * 4096 + s * 256 + t];
    float a = sign * Sv;
    sA[t] = fabsf(a);
    __syncthreads();
    if (j == 0) {
        float rs = 0.f;
        #pragma unroll
        for (int k = 0; k < 16; k++) rs += sA[i * 16 + k];
        rowsum[i] = rs;
    }
    __syncthreads();
    if (t == 0) {
        float mx = 0.f;
        #pragma unroll
        for (int k = 0; k < 16; k++) mx = fmaxf(mx, rowsum[k]);
        int s = 0;
        while (mx > 0.25f && s < 60) { mx *= 0.5f; s++; }
        s_sq = s;
    }
    __syncthreads();
    int s = s_sq;
    a = ldexpf(a, -s);
    sA[t] = a;
    sT[t] = a;
    float p = ((i == j) ? 1.0f : 0.0f) + a;
    __syncthreads();
    for (int k = 2; k <= 7; k++) {
        float nt = 0.f;
        #pragma unroll
        for (int kk = 0; kk < 16; kk++)
            nt += sT[i * 16 + kk] * sA[kk * 16 + j];
        nt *= (1.0f / (float)k);
        __syncthreads();
        sT[t] = nt;
        p += nt;
        __syncthreads();
    }
    for (int it = 0; it < s; it++) {
        sP[t] = p;
        __syncthreads();
        float np = 0.f;
        #pragma unroll
        for (int kk = 0; kk < 16; kk++)
            np += sP[i * 16 + kk] * sP[kk * 16 + j];
        p = np;
        __syncthreads();
    }
    sP[t] = p;               // final expm in shared
    if (!invm) out[OUT_FWD + m * 256 + t] = p;
    __syncthreads();

    // fused tz half: tz1 for fwd blocks, tz2 for inv blocks
    if (t < 16) {
        int d = t;
        float v = 0.f, dd;
        if (!invm) {
            #pragma unroll
            for (int k = 0; k < 16; k++)
                v += z[m * 16 + k] * sP[k * 16 + d];
            out[OUT_TZ1 + m * 16 + d] = v;
            dd = v - z[(64 + m) * 16 + d];   // tz1 - z2
        } else {
            #pragma unroll
            for (int k = 0; k < 16; k++)
                v += z[(64 + m) * 16 + k] * sP[k * 16 + d];
            out[OUT_TZ2 + m * 16 + d] = v;
            dd = v - z[m * 16 + d];          // tz2 - z1
        }
        float term = dd * dd;
        #pragma unroll
        for (int o = 8; o; o >>= 1) term += __shfl_xor_sync(0xffffu, term, o);
        if (t == 0) atomicAdd(&g_acc[ACC_EQ], (double)term);
    }
    __syncthreads();

    // last-finished block writes final scalar outputs
    if (t == 0) {
        __threadfence();
        unsigned int old = atomicAdd(&g_done, 1);
        if (old == 127) {
            __threadfence();
            out[OUT_PAR]    = (float)(g_acc[ACC_PAR] / (16.0 * 2048.0 * 2048.0));
            out[OUT_ORTH]   = (float)(2.0 * g_acc[ACC_ORTH] / (2048.0 * 2048.0));
            out[OUT_SPARSE] = (float)(g_acc[ACC_SPARSE] / 32768.0);
            out[OUT_SECTOR] = (float)(g_acc[ACC_SECTOR] / 64.0);
            out[OUT_EQ]     = (float)(g_acc[ACC_EQ] / 1024.0);
            out[OUT_COMMUT] = (float)(g_acc[ACC_COMMUT] / (4096.0 * 4096.0));
        }
    }
}

extern "C" void kernel_launch(void* const* d_in, const int* in_sizes, int n_in,
                              void* d_out, int out_size)
{
    // resolve inputs by element count (robust to metadata ordering)
    int ige = -1, ilw = -1, ilb = -1, isx = -1;
    int i2048[4]; int n2 = 0;
    for (int i = 0; i < n_in; i++) {
        int sz = in_sizes[i];
        if (sz == 65536) ige = i;
        else if (sz == 18432) ilw = i;
        else if (sz == 288) ilb = i;
        else if (sz == 16) isx = i;
        else if (sz == 2048 && n2 < 4) i2048[n2++] = i;
    }
    int imean, ilogvar, iz, ign;
    if (ige == 0) {
        ign = i2048[0]; iz = i2048[1]; ilogvar = i2048[2]; imean = i2048[3];
    } else {
        imean = i2048[0]; ilogvar = i2048[1]; iz = i2048[2]; ign = i2048[3];
    }

    const float* mean   = (const float*)d_in[imean];
    const float* logvar = (const float*)d_in[ilogvar];
    const float* z      = (const float*)d_in[iz];
    const float* ge     = (const float*)d_in[ige];
    const float* lw     = (const float*)d_in[ilw];
    const float* lb     = (const float*)d_in[ilb];
    const float* gn     = (const float*)d_in[ign];
    const int*   sidx   = (const int*)d_in[isx];
    float* out = (float*)d_out;

    static void* accPtr = nullptr;
    if (!accPtr) cudaGetSymbolAddress(&accPtr, g_acc);

    cudaMemsetAsync(accPtr, 0, 8 * sizeof(double), 0);
    k_stage1<<<440, 256>>>(ge, z, mean, logvar, lw, lb, gn, out);
    k_stage2<<<1224, 256>>>(sidx, ge, out);
    k_stage3<<<128, 256>>>(z, out);
}